// round 4
// baseline (speedup 1.0000x reference)
#include <cuda_runtime.h>
#include <cuda_fp16.h>

#define USER_NUM 50000
#define N_NODES  100000
#define EMB      64
#define ADJ_NNZ  1600000
#define S_NNZ    800000
#define TOT      (N_NODES * EMB)
#define SB 512
#define ADJ_NB ((N_NODES + SB - 1) / SB)    // 196
#define S_NB   ((USER_NUM + SB - 1) / SB)   // 98

// ---------------- scratch (device globals; zero-initialized at load) ----------------
__device__ __half g_egoA[TOT];
__device__ __half g_egoB[TOT];
__device__ __half g_h[USER_NUM * EMB];
__device__ float  g_acc[TOT];

__device__ int   g_adj_cnt[N_NODES];        // invariant: zero at kernel_launch entry
__device__ int   g_adj_ptr[N_NODES + 1];
__device__ int   g_adj_w[N_NODES];
__device__ uint2 g_adj_cv[ADJ_NNZ];

__device__ int   g_s_cnt[USER_NUM];         // invariant: zero at kernel_launch entry
__device__ int   g_s_ptr[USER_NUM + 1];
__device__ int   g_s_w[USER_NUM];
__device__ uint2 g_s_cv[S_NNZ];

__device__ int   g_bsumsA[SB];
__device__ int   g_bsumsB[SB];

// ---------------- fused: hist(adj) + hist(s) + init(ego, acc) ----------------
__global__ void hist_init_kernel(const int* __restrict__ adj_rows, const int* __restrict__ s_rows,
                                 int* __restrict__ adj_cnt, int* __restrict__ s_cnt,
                                 const float* __restrict__ ue, const float* __restrict__ ie,
                                 __half* __restrict__ ego, float* __restrict__ acc) {
    int i = blockIdx.x * blockDim.x + threadIdx.x;
    if (i < ADJ_NNZ) {
        atomicAdd(adj_cnt + __ldcs(adj_rows + i), 1);
    } else if (i < ADJ_NNZ + S_NNZ) {
        atomicAdd(s_cnt + __ldcs(s_rows + (i - ADJ_NNZ)), 1);
    } else if (i < ADJ_NNZ + S_NNZ + TOT / 2) {
        int j = i - (ADJ_NNZ + S_NNZ);             // half2/float2 index
        const float2* src = (j < USER_NUM * EMB / 2) ? (const float2*)ue
                                                     : (const float2*)ie - USER_NUM * EMB / 2;
        float2 v = src[j];
        ((__half2*)ego)[j] = __floats2half2_rn(v.x, v.y);
        ((float2*)acc)[j] = v;
    }
}

// per-block exclusive scans of both count arrays (blocks [0,ADJ_NB) -> adj, rest -> s)
__global__ void scan1_kernel(const int* __restrict__ adj_cnt, int* __restrict__ adj_ptr,
                             const int* __restrict__ s_cnt, int* __restrict__ s_ptr,
                             int* __restrict__ bsumsA, int* __restrict__ bsumsB) {
    __shared__ int sh[SB];
    const int* cnt; int* ptr; int* bsums; int n; int b;
    if (blockIdx.x < ADJ_NB) { cnt = adj_cnt; ptr = adj_ptr; bsums = bsumsA; n = N_NODES; b = blockIdx.x; }
    else                     { cnt = s_cnt;   ptr = s_ptr;   bsums = bsumsB; n = USER_NUM; b = blockIdx.x - ADJ_NB; }
    int i = b * SB + threadIdx.x;
    int v = (i < n) ? cnt[i] : 0;
    sh[threadIdx.x] = v;
    __syncthreads();
    for (int off = 1; off < SB; off <<= 1) {
        int t = (threadIdx.x >= off) ? sh[threadIdx.x - off] : 0;
        __syncthreads();
        sh[threadIdx.x] += t;
        __syncthreads();
    }
    if (i < n) ptr[i] = sh[threadIdx.x] - v;
    if (threadIdx.x == SB - 1) bsums[b] = sh[SB - 1];
}

// scan both block-sum arrays (block 0 -> A, block 1 -> B)
__global__ void scan2_kernel(int* __restrict__ bsumsA, int* __restrict__ bsumsB) {
    __shared__ int sh[SB];
    int* bs = (blockIdx.x == 0) ? bsumsA : bsumsB;
    int nb  = (blockIdx.x == 0) ? ADJ_NB : S_NB;
    int v = (threadIdx.x < nb) ? bs[threadIdx.x] : 0;
    sh[threadIdx.x] = v;
    __syncthreads();
    for (int off = 1; off < SB; off <<= 1) {
        int t = (threadIdx.x >= off) ? sh[threadIdx.x - off] : 0;
        __syncthreads();
        sh[threadIdx.x] += t;
        __syncthreads();
    }
    if (threadIdx.x < nb) bs[threadIdx.x] = sh[threadIdx.x] - v;
}

// add block offsets, seed working offsets, terminate rowptrs, RE-ZERO cnt arrays
__global__ void scan3_kernel(int* __restrict__ adj_ptr, int* __restrict__ adj_w,
                             int* __restrict__ s_ptr, int* __restrict__ s_w,
                             const int* __restrict__ bsumsA, const int* __restrict__ bsumsB,
                             int* __restrict__ adj_cnt, int* __restrict__ s_cnt) {
    int i = blockIdx.x * blockDim.x + threadIdx.x;
    if (i < N_NODES) {
        int p = adj_ptr[i] + bsumsA[i / SB];
        adj_ptr[i] = p; adj_w[i] = p; adj_cnt[i] = 0;
        if (i == 0) adj_ptr[N_NODES] = ADJ_NNZ;
    } else if (i < N_NODES + USER_NUM) {
        int j = i - N_NODES;
        int p = s_ptr[j] + bsumsB[j / SB];
        s_ptr[j] = p; s_w[j] = p; s_cnt[j] = 0;
        if (j == 0) s_ptr[USER_NUM] = S_NNZ;
    }
}

// scatter both edge lists into packed (col,val) CSR payload
__global__ void scatter_kernel(const int* __restrict__ adj_rows, const int* __restrict__ adj_cols,
                               const float* __restrict__ adj_vals, int* __restrict__ adj_w,
                               uint2* __restrict__ adj_cv,
                               const int* __restrict__ s_rows, const int* __restrict__ s_cols,
                               const float* __restrict__ s_vals, int* __restrict__ s_w,
                               uint2* __restrict__ s_cv) {
    int i = blockIdx.x * blockDim.x + threadIdx.x;
    if (i < ADJ_NNZ) {
        int p = atomicAdd(adj_w + __ldcs(adj_rows + i), 1);
        adj_cv[p] = make_uint2((unsigned)__ldcs(adj_cols + i), __float_as_uint(__ldcs(adj_vals + i)));
    } else if (i < ADJ_NNZ + S_NNZ) {
        int j = i - ADJ_NNZ;
        int p = atomicAdd(s_w + __ldcs(s_rows + j), 1);
        s_cv[p] = make_uint2((unsigned)__ldcs(s_cols + j), __float_as_uint(__ldcs(s_vals + j)));
    }
}

// ---------------- warp-per-row gather core ----------------
// Lane-cooperative cv fetch (32 edges per coalesced load), shfl broadcast,
// MLP-8 gather batches with deferred FMAs. Inactive lanes -> (col 0, w 0): harmless.
template <bool DUAL>
__device__ __forceinline__ float2 row_accum(const uint2* __restrict__ cv, int e0, int end,
                                            int lane, const __half* __restrict__ ego,
                                            const __half* __restrict__ h, float2 a) {
    for (int base = e0; base < end; base += 32) {
        uint2 my = (base + lane < end) ? __ldg(cv + base + lane) : make_uint2(0u, 0u);
        int n = min(32, end - base);
        for (int j = 0; j < n; j += 8) {
            float2 x[8];
            float  w[8];
#pragma unroll
            for (int k = 0; k < 8; k++) {
                unsigned c = __shfl_sync(0xffffffffu, my.x, j + k);
                w[k] = __uint_as_float(__shfl_sync(0xffffffffu, my.y, j + k));
                const __half* b = (DUAL && c < USER_NUM) ? h : ego;
                x[k] = __half22float2(__ldg((const __half2*)(b + (size_t)c * EMB) + lane));
            }
#pragma unroll
            for (int k = 0; k < 8; k++) {
                a.x = fmaf(w[k], x[k].x, a.x);
                a.y = fmaf(w[k], x[k].y, a.y);
            }
        }
    }
    return a;
}

// h[r] = ego[r] + sum val*ego[col]   (users)
__global__ void s_spmm_kernel(const int* __restrict__ ptr, const uint2* __restrict__ cv,
                              const __half* __restrict__ ego, __half* __restrict__ h) {
    int row = blockIdx.x * (blockDim.x >> 5) + (threadIdx.x >> 5);
    int lane = threadIdx.x & 31;
    if (row >= USER_NUM) return;
    int e0 = __ldg(ptr + row), end = __ldg(ptr + row + 1);
    float2 a = __half22float2(((const __half2*)(ego + (size_t)row * EMB))[lane]); // self term
    a = row_accum<false>(cv, e0, end, lane, ego, ego, a);
    ((__half2*)(h + (size_t)row * EMB))[lane] = __floats2half2_rn(a.x, a.y);
}

// nxt[r] = sum val*sel(col); sel = h (users) / ego (items)
// last==0: nxt=half(v), acc+=v ; last==1: out=(acc+v)*0.25 (fp32)
__global__ void adj_spmm_kernel(const int* __restrict__ ptr, const uint2* __restrict__ cv,
                                const __half* __restrict__ ego, const __half* __restrict__ h,
                                __half* __restrict__ nxt, float* __restrict__ acc,
                                float* __restrict__ out, int last) {
    int row = blockIdx.x * (blockDim.x >> 5) + (threadIdx.x >> 5);
    int lane = threadIdx.x & 31;
    if (row >= N_NODES) return;
    int e0 = __ldg(ptr + row), end = __ldg(ptr + row + 1);
    float2 a = row_accum<true>(cv, e0, end, lane, ego, h, make_float2(0.f, 0.f));
    float2 ac = ((const float2*)(acc + (size_t)row * EMB))[lane];
    if (last) {
        ((float2*)(out + (size_t)row * EMB))[lane] =
            make_float2((ac.x + a.x) * 0.25f, (ac.y + a.y) * 0.25f);
    } else {
        ((__half2*)(nxt + (size_t)row * EMB))[lane] = __floats2half2_rn(a.x, a.y);
        ((float2*)(acc + (size_t)row * EMB))[lane] = make_float2(ac.x + a.x, ac.y + a.y);
    }
}

extern "C" void kernel_launch(void* const* d_in, const int* in_sizes, int n_in,
                              void* d_out, int out_size) {
    const float* ue       = (const float*)d_in[0];
    const float* ie       = (const float*)d_in[1];
    const int*   adj_rows = (const int*)d_in[2];
    const int*   adj_cols = (const int*)d_in[3];
    const float* adj_vals = (const float*)d_in[4];
    const int*   s_rows   = (const int*)d_in[5];
    const int*   s_cols   = (const int*)d_in[6];
    const float* s_vals   = (const float*)d_in[7];

    __half *egoA, *egoB, *h;
    float *acc;
    int *adj_cnt, *adj_ptr, *adj_w, *s_cnt, *s_ptr, *s_w, *bsumsA, *bsumsB;
    uint2 *adj_cv, *s_cv;
    cudaGetSymbolAddress((void**)&egoA,    g_egoA);
    cudaGetSymbolAddress((void**)&egoB,    g_egoB);
    cudaGetSymbolAddress((void**)&h,       g_h);
    cudaGetSymbolAddress((void**)&acc,     g_acc);
    cudaGetSymbolAddress((void**)&adj_cnt, g_adj_cnt);
    cudaGetSymbolAddress((void**)&adj_ptr, g_adj_ptr);
    cudaGetSymbolAddress((void**)&adj_w,   g_adj_w);
    cudaGetSymbolAddress((void**)&adj_cv,  g_adj_cv);
    cudaGetSymbolAddress((void**)&s_cnt,   g_s_cnt);
    cudaGetSymbolAddress((void**)&s_ptr,   g_s_ptr);
    cudaGetSymbolAddress((void**)&s_w,     g_s_w);
    cudaGetSymbolAddress((void**)&s_cv,    g_s_cv);
    cudaGetSymbolAddress((void**)&bsumsA,  g_bsumsA);
    cudaGetSymbolAddress((void**)&bsumsB,  g_bsumsB);

    const int TPB = 256;

    // ---- build CSR for both matrices + init embeddings (5 kernels) ----
    {
        int tot = ADJ_NNZ + S_NNZ + TOT / 2;
        hist_init_kernel<<<(tot + TPB - 1) / TPB, TPB>>>(adj_rows, s_rows, adj_cnt, s_cnt,
                                                         ue, ie, egoA, acc);
    }
    scan1_kernel<<<ADJ_NB + S_NB, SB>>>(adj_cnt, adj_ptr, s_cnt, s_ptr, bsumsA, bsumsB);
    scan2_kernel<<<2, SB>>>(bsumsA, bsumsB);
    {
        int tot = N_NODES + USER_NUM;
        scan3_kernel<<<(tot + TPB - 1) / TPB, TPB>>>(adj_ptr, adj_w, s_ptr, s_w,
                                                     bsumsA, bsumsB, adj_cnt, s_cnt);
    }
    {
        int tot = ADJ_NNZ + S_NNZ;
        scatter_kernel<<<(tot + TPB - 1) / TPB, TPB>>>(adj_rows, adj_cols, adj_vals, adj_w, adj_cv,
                                                       s_rows, s_cols, s_vals, s_w, s_cv);
    }

    // ---- 3 layers (6 kernels) ----
    __half* ego = egoA;
    __half* nxt = egoB;
    const int wpb = TPB / 32;
    const int s_blocks   = (USER_NUM + wpb - 1) / wpb;
    const int adj_blocks = (N_NODES + wpb - 1) / wpb;
    for (int l = 0; l < 3; l++) {
        s_spmm_kernel<<<s_blocks, TPB>>>(s_ptr, s_cv, ego, h);
        adj_spmm_kernel<<<adj_blocks, TPB>>>(adj_ptr, adj_cv, ego, h,
                                             nxt, acc, (float*)d_out, (l == 2) ? 1 : 0);
        __half* t = ego; ego = nxt; nxt = t;
    }
}

// round 5
// speedup vs baseline: 1.1859x; 1.1859x over previous
#include <cuda_runtime.h>
#include <cuda_fp16.h>

#define USER_NUM 50000
#define N_NODES  100000
#define EMB      64
#define ADJ_NNZ  1600000
#define S_NNZ    800000
#define TOT      (N_NODES * EMB)
#define SB 512
#define ADJ_NB ((N_NODES + SB - 1) / SB)    // 196
#define S_NB   ((USER_NUM + SB - 1) / SB)   // 98

// ---------------- scratch (device globals; zero-initialized at load) ----------------
__device__ __half g_egoA[TOT];
__device__ __half g_egoB[TOT];
__device__ __half g_h[USER_NUM * EMB];
__device__ float  g_acc[TOT];

__device__ int   g_adj_cnt[N_NODES];        // invariant: zero at kernel_launch entry
__device__ int   g_adj_ptr[N_NODES + 1];
__device__ int   g_adj_w[N_NODES];
__device__ uint2 g_adj_cv[ADJ_NNZ];

__device__ int   g_s_cnt[USER_NUM];         // invariant: zero at kernel_launch entry
__device__ int   g_s_ptr[USER_NUM + 1];
__device__ int   g_s_w[USER_NUM];
__device__ uint2 g_s_cv[S_NNZ];

__device__ int   g_bsumsA[SB];
__device__ int   g_bsumsB[SB];

// ---------------- fused: hist(adj) + hist(s) + init(ego, acc) ----------------
__global__ void hist_init_kernel(const int* __restrict__ adj_rows, const int* __restrict__ s_rows,
                                 int* __restrict__ adj_cnt, int* __restrict__ s_cnt,
                                 const float* __restrict__ ue, const float* __restrict__ ie,
                                 __half* __restrict__ ego, float* __restrict__ acc) {
    int i = blockIdx.x * blockDim.x + threadIdx.x;
    if (i < ADJ_NNZ) {
        atomicAdd(adj_cnt + __ldcs(adj_rows + i), 1);
    } else if (i < ADJ_NNZ + S_NNZ) {
        atomicAdd(s_cnt + __ldcs(s_rows + (i - ADJ_NNZ)), 1);
    } else if (i < ADJ_NNZ + S_NNZ + TOT / 2) {
        int j = i - (ADJ_NNZ + S_NNZ);             // half2/float2 index
        const float2* src = (j < USER_NUM * EMB / 2) ? (const float2*)ue
                                                     : (const float2*)ie - USER_NUM * EMB / 2;
        float2 v = src[j];
        ((__half2*)ego)[j] = __floats2half2_rn(v.x, v.y);
        ((float2*)acc)[j] = v;
    }
}

// per-block exclusive scans of both count arrays
__global__ void scan1_kernel(const int* __restrict__ adj_cnt, int* __restrict__ adj_ptr,
                             const int* __restrict__ s_cnt, int* __restrict__ s_ptr,
                             int* __restrict__ bsumsA, int* __restrict__ bsumsB) {
    __shared__ int sh[SB];
    const int* cnt; int* ptr; int* bsums; int n; int b;
    if (blockIdx.x < ADJ_NB) { cnt = adj_cnt; ptr = adj_ptr; bsums = bsumsA; n = N_NODES; b = blockIdx.x; }
    else                     { cnt = s_cnt;   ptr = s_ptr;   bsums = bsumsB; n = USER_NUM; b = blockIdx.x - ADJ_NB; }
    int i = b * SB + threadIdx.x;
    int v = (i < n) ? cnt[i] : 0;
    sh[threadIdx.x] = v;
    __syncthreads();
    for (int off = 1; off < SB; off <<= 1) {
        int t = (threadIdx.x >= off) ? sh[threadIdx.x - off] : 0;
        __syncthreads();
        sh[threadIdx.x] += t;
        __syncthreads();
    }
    if (i < n) ptr[i] = sh[threadIdx.x] - v;
    if (threadIdx.x == SB - 1) bsums[b] = sh[SB - 1];
}

__global__ void scan2_kernel(int* __restrict__ bsumsA, int* __restrict__ bsumsB) {
    __shared__ int sh[SB];
    int* bs = (blockIdx.x == 0) ? bsumsA : bsumsB;
    int nb  = (blockIdx.x == 0) ? ADJ_NB : S_NB;
    int v = (threadIdx.x < nb) ? bs[threadIdx.x] : 0;
    sh[threadIdx.x] = v;
    __syncthreads();
    for (int off = 1; off < SB; off <<= 1) {
        int t = (threadIdx.x >= off) ? sh[threadIdx.x - off] : 0;
        __syncthreads();
        sh[threadIdx.x] += t;
        __syncthreads();
    }
    if (threadIdx.x < nb) bs[threadIdx.x] = sh[threadIdx.x] - v;
}

// add block offsets, seed working offsets, terminate rowptrs, re-zero cnt arrays
__global__ void scan3_kernel(int* __restrict__ adj_ptr, int* __restrict__ adj_w,
                             int* __restrict__ s_ptr, int* __restrict__ s_w,
                             const int* __restrict__ bsumsA, const int* __restrict__ bsumsB,
                             int* __restrict__ adj_cnt, int* __restrict__ s_cnt) {
    int i = blockIdx.x * blockDim.x + threadIdx.x;
    if (i < N_NODES) {
        int p = adj_ptr[i] + bsumsA[i / SB];
        adj_ptr[i] = p; adj_w[i] = p; adj_cnt[i] = 0;
        if (i == 0) adj_ptr[N_NODES] = ADJ_NNZ;
    } else if (i < N_NODES + USER_NUM) {
        int j = i - N_NODES;
        int p = s_ptr[j] + bsumsB[j / SB];
        s_ptr[j] = p; s_w[j] = p; s_cnt[j] = 0;
        if (j == 0) s_ptr[USER_NUM] = S_NNZ;
    }
}

// scatter both edge lists into packed (col,val) CSR payload
__global__ void scatter_kernel(const int* __restrict__ adj_rows, const int* __restrict__ adj_cols,
                               const float* __restrict__ adj_vals, int* __restrict__ adj_w,
                               uint2* __restrict__ adj_cv,
                               const int* __restrict__ s_rows, const int* __restrict__ s_cols,
                               const float* __restrict__ s_vals, int* __restrict__ s_w,
                               uint2* __restrict__ s_cv) {
    int i = blockIdx.x * blockDim.x + threadIdx.x;
    if (i < ADJ_NNZ) {
        int p = atomicAdd(adj_w + __ldcs(adj_rows + i), 1);
        adj_cv[p] = make_uint2((unsigned)__ldcs(adj_cols + i), __float_as_uint(__ldcs(adj_vals + i)));
    } else if (i < ADJ_NNZ + S_NNZ) {
        int j = i - ADJ_NNZ;
        int p = atomicAdd(s_w + __ldcs(s_rows + j), 1);
        s_cv[p] = make_uint2((unsigned)__ldcs(s_cols + j), __float_as_uint(__ldcs(s_vals + j)));
    }
}

// ---------------- warp-per-row gather core (direct cv loads, MLP-4) ----------------
template <bool DUAL>
__device__ __forceinline__ float2 row_accum(const uint2* __restrict__ cv, int e, int end,
                                            int lane, const __half* __restrict__ ego,
                                            const __half* __restrict__ h, float2 a) {
    // main loop: 4 edges per iteration, gathers issued before FMAs (MLP=4)
    for (; e + 3 < end; e += 4) {
        uint2 cv0 = __ldg(cv + e),     cv1 = __ldg(cv + e + 1);
        uint2 cv2 = __ldg(cv + e + 2), cv3 = __ldg(cv + e + 3);
        const __half* b0 = (DUAL && cv0.x < USER_NUM) ? h : ego;
        const __half* b1 = (DUAL && cv1.x < USER_NUM) ? h : ego;
        const __half* b2 = (DUAL && cv2.x < USER_NUM) ? h : ego;
        const __half* b3 = (DUAL && cv3.x < USER_NUM) ? h : ego;
        float2 x0 = __half22float2(__ldg((const __half2*)(b0 + (size_t)cv0.x * EMB) + lane));
        float2 x1 = __half22float2(__ldg((const __half2*)(b1 + (size_t)cv1.x * EMB) + lane));
        float2 x2 = __half22float2(__ldg((const __half2*)(b2 + (size_t)cv2.x * EMB) + lane));
        float2 x3 = __half22float2(__ldg((const __half2*)(b3 + (size_t)cv3.x * EMB) + lane));
        float w0 = __uint_as_float(cv0.y), w1 = __uint_as_float(cv1.y);
        float w2 = __uint_as_float(cv2.y), w3 = __uint_as_float(cv3.y);
        a.x = fmaf(w0, x0.x, fmaf(w1, x1.x, fmaf(w2, x2.x, fmaf(w3, x3.x, a.x))));
        a.y = fmaf(w0, x0.y, fmaf(w1, x1.y, fmaf(w2, x2.y, fmaf(w3, x3.y, a.y))));
    }
    for (; e < end; e++) {
        uint2 cv0 = __ldg(cv + e);
        float w0 = __uint_as_float(cv0.y);
        const __half* b0 = (DUAL && cv0.x < USER_NUM) ? h : ego;
        float2 x0 = __half22float2(__ldg((const __half2*)(b0 + (size_t)cv0.x * EMB) + lane));
        a.x = fmaf(w0, x0.x, a.x);
        a.y = fmaf(w0, x0.y, a.y);
    }
    return a;
}

// h[r] = ego[r] + sum val*ego[col]   (users)
__global__ void s_spmm_kernel(const int* __restrict__ ptr, const uint2* __restrict__ cv,
                              const __half* __restrict__ ego, __half* __restrict__ h) {
    int row = blockIdx.x * (blockDim.x >> 5) + (threadIdx.x >> 5);
    int lane = threadIdx.x & 31;
    if (row >= USER_NUM) return;
    int e0 = __ldg(ptr + row), end = __ldg(ptr + row + 1);
    float2 a = __half22float2(((const __half2*)(ego + (size_t)row * EMB))[lane]); // self term
    a = row_accum<false>(cv, e0, end, lane, ego, ego, a);
    ((__half2*)(h + (size_t)row * EMB))[lane] = __floats2half2_rn(a.x, a.y);
}

// nxt[r] = sum val*sel(col); sel = h (users) / ego (items)
// last==0: nxt=half(v), acc+=v ; last==1: out=(acc+v)*0.25 (fp32)
__global__ void adj_spmm_kernel(const int* __restrict__ ptr, const uint2* __restrict__ cv,
                                const __half* __restrict__ ego, const __half* __restrict__ h,
                                __half* __restrict__ nxt, float* __restrict__ acc,
                                float* __restrict__ out, int last) {
    int row = blockIdx.x * (blockDim.x >> 5) + (threadIdx.x >> 5);
    int lane = threadIdx.x & 31;
    if (row >= N_NODES) return;
    int e0 = __ldg(ptr + row), end = __ldg(ptr + row + 1);
    float2 a = row_accum<true>(cv, e0, end, lane, ego, h, make_float2(0.f, 0.f));
    float2 ac = ((const float2*)(acc + (size_t)row * EMB))[lane];
    if (last) {
        ((float2*)(out + (size_t)row * EMB))[lane] =
            make_float2((ac.x + a.x) * 0.25f, (ac.y + a.y) * 0.25f);
    } else {
        ((__half2*)(nxt + (size_t)row * EMB))[lane] = __floats2half2_rn(a.x, a.y);
        ((float2*)(acc + (size_t)row * EMB))[lane] = make_float2(ac.x + a.x, ac.y + a.y);
    }
}

extern "C" void kernel_launch(void* const* d_in, const int* in_sizes, int n_in,
                              void* d_out, int out_size) {
    const float* ue       = (const float*)d_in[0];
    const float* ie       = (const float*)d_in[1];
    const int*   adj_rows = (const int*)d_in[2];
    const int*   adj_cols = (const int*)d_in[3];
    const float* adj_vals = (const float*)d_in[4];
    const int*   s_rows   = (const int*)d_in[5];
    const int*   s_cols   = (const int*)d_in[6];
    const float* s_vals   = (const float*)d_in[7];

    __half *egoA, *egoB, *h;
    float *acc;
    int *adj_cnt, *adj_ptr, *adj_w, *s_cnt, *s_ptr, *s_w, *bsumsA, *bsumsB;
    uint2 *adj_cv, *s_cv;
    cudaGetSymbolAddress((void**)&egoA,    g_egoA);
    cudaGetSymbolAddress((void**)&egoB,    g_egoB);
    cudaGetSymbolAddress((void**)&h,       g_h);
    cudaGetSymbolAddress((void**)&acc,     g_acc);
    cudaGetSymbolAddress((void**)&adj_cnt, g_adj_cnt);
    cudaGetSymbolAddress((void**)&adj_ptr, g_adj_ptr);
    cudaGetSymbolAddress((void**)&adj_w,   g_adj_w);
    cudaGetSymbolAddress((void**)&adj_cv,  g_adj_cv);
    cudaGetSymbolAddress((void**)&s_cnt,   g_s_cnt);
    cudaGetSymbolAddress((void**)&s_ptr,   g_s_ptr);
    cudaGetSymbolAddress((void**)&s_w,     g_s_w);
    cudaGetSymbolAddress((void**)&s_cv,    g_s_cv);
    cudaGetSymbolAddress((void**)&bsumsA,  g_bsumsA);
    cudaGetSymbolAddress((void**)&bsumsB,  g_bsumsB);

    const int TPB = 256;

    // ---- build CSR for both matrices + init embeddings (5 kernels) ----
    {
        int tot = ADJ_NNZ + S_NNZ + TOT / 2;
        hist_init_kernel<<<(tot + TPB - 1) / TPB, TPB>>>(adj_rows, s_rows, adj_cnt, s_cnt,
                                                         ue, ie, egoA, acc);
    }
    scan1_kernel<<<ADJ_NB + S_NB, SB>>>(adj_cnt, adj_ptr, s_cnt, s_ptr, bsumsA, bsumsB);
    scan2_kernel<<<2, SB>>>(bsumsA, bsumsB);
    {
        int tot = N_NODES + USER_NUM;
        scan3_kernel<<<(tot + TPB - 1) / TPB, TPB>>>(adj_ptr, adj_w, s_ptr, s_w,
                                                     bsumsA, bsumsB, adj_cnt, s_cnt);
    }
    {
        int tot = ADJ_NNZ + S_NNZ;
        scatter_kernel<<<(tot + TPB - 1) / TPB, TPB>>>(adj_rows, adj_cols, adj_vals, adj_w, adj_cv,
                                                       s_rows, s_cols, s_vals, s_w, s_cv);
    }

    // ---- 3 layers (6 kernels) ----
    __half* ego = egoA;
    __half* nxt = egoB;
    const int wpb = TPB / 32;
    const int s_blocks   = (USER_NUM + wpb - 1) / wpb;
    const int adj_blocks = (N_NODES + wpb - 1) / wpb;
    for (int l = 0; l < 3; l++) {
        s_spmm_kernel<<<s_blocks, TPB>>>(s_ptr, s_cv, ego, h);
        adj_spmm_kernel<<<adj_blocks, TPB>>>(adj_ptr, adj_cv, ego, h,
                                             nxt, acc, (float*)d_out, (l == 2) ? 1 : 0);
        __half* t = ego; ego = nxt; nxt = t;
    }
}